// round 3
// baseline (speedup 1.0000x reference)
#include <cuda_runtime.h>
#include <math.h>
#include <stdint.h>

#define FEAT 128
#define OUTF 16
#define NMAX 50000
#define EMAX 800000
#define BN_EPS 1e-5f

// ---------------- scratch (no allocations allowed) ----------------
__device__ float g_h[(size_t)NMAX * FEAT];     // GEMM output (layer3 reuses as [n,16])
__device__ float g_x2[(size_t)NMAX * FEAT];    // post-aggregation activation
__device__ int   g_deg[NMAX];
__device__ int   g_rowptr[NMAX + 1];
__device__ int   g_cursor[NMAX];
__device__ float g_dinv[NMAX];
__device__ int   g_csr_src[EMAX];
__device__ float g_csr_norm[EMAX];
__device__ float g_S[2 * FEAT];
__device__ float g_T[2 * FEAT];
__device__ int   g_blksum[1024];

// ---------------- degree / dinv ----------------
__global__ void k_zero_deg(int n) {
    int i = blockIdx.x * blockDim.x + threadIdx.x;
    if (i < n) g_deg[i] = 0;
}

// edge_index is int32 (JAX default x64-disabled demotes int64 -> int32).
__global__ void k_count(const int* __restrict__ ei, int e, int n) {
    int i = blockIdx.x * blockDim.x + threadIdx.x;
    if (i < e) {
        int d = ei[e + i];
        d = min(max(d, 0), n - 1);  // no-op on valid data; guards vs dtype surprise
        atomicAdd(&g_deg[d], 1);
    }
}

__global__ void k_dinv(int n) {
    int i = blockIdx.x * blockDim.x + threadIdx.x;
    if (i < n) g_dinv[i] = rsqrtf((float)(g_deg[i] + 1));  // +1 = self loop, deg>=1
}

// ---------------- 3-kernel exclusive scan of deg -> rowptr ----------------
__global__ void k_scan1(int n) {  // 1024 threads/block: per-block sums
    __shared__ int sm[1024];
    int t = threadIdx.x;
    int i = blockIdx.x * 1024 + t;
    sm[t] = (i < n) ? g_deg[i] : 0;
    __syncthreads();
    for (int off = 512; off > 0; off >>= 1) {
        if (t < off) sm[t] += sm[t + off];
        __syncthreads();
    }
    if (t == 0) g_blksum[blockIdx.x] = sm[0];
}

__global__ void k_scan2(int nb, int n) {  // <<<1,1>>>
    int running = 0;
    for (int b = 0; b < nb; b++) {
        int v = g_blksum[b];
        g_blksum[b] = running;
        running += v;
    }
    g_rowptr[n] = running;
}

__global__ void k_scan3(int n) {  // 1024 threads: block exclusive scan + offset
    __shared__ int sm[1024];
    int t = threadIdx.x;
    int i = blockIdx.x * 1024 + t;
    int v = (i < n) ? g_deg[i] : 0;
    sm[t] = v;
    __syncthreads();
    for (int off = 1; off < 1024; off <<= 1) {
        int u = 0;
        if (t >= off) u = sm[t - off];
        __syncthreads();
        sm[t] += u;
        __syncthreads();
    }
    if (i < n) {
        int excl = g_blksum[blockIdx.x] + sm[t] - v;
        g_rowptr[i] = excl;
        g_cursor[i] = excl;
    }
}

__global__ void k_fill(const int* __restrict__ ei, int e, int n) {
    int i = blockIdx.x * blockDim.x + threadIdx.x;
    if (i < e) {
        int s = ei[i];
        int d = ei[e + i];
        s = min(max(s, 0), n - 1);
        d = min(max(d, 0), n - 1);
        int p = atomicAdd(&g_cursor[d], 1);
        g_csr_src[p]  = s;
        g_csr_norm[p] = g_dinv[s] * g_dinv[d];
    }
}

// ---------------- precompute fused BN affine: out = relu(acc*S + T) ----------------
__global__ void k_prep(const float* __restrict__ b1, const float* __restrict__ g1,
                       const float* __restrict__ be1, const float* __restrict__ m1,
                       const float* __restrict__ v1,
                       const float* __restrict__ b2, const float* __restrict__ g2,
                       const float* __restrict__ be2, const float* __restrict__ m2,
                       const float* __restrict__ v2) {
    int t = threadIdx.x;
    if (t < FEAT) {
        float s = rsqrtf(v1[t] + BN_EPS) * g1[t];
        g_S[t] = s;
        g_T[t] = (b1[t] - m1[t]) * s + be1[t];
    } else {
        int c = t - FEAT;
        float s = rsqrtf(v2[c] + BN_EPS) * g2[c];
        g_S[FEAT + c] = s;
        g_T[FEAT + c] = (b2[c] - m2[c]) * s + be2[c];
    }
}

// ---------------- GEMM: C[n,128] = X[n,128] @ W[128,128] ----------------
// Block: 256 threads, 64 rows x 128 cols. X tile staged in smem (32x reuse),
// W rows read through L1/L2 (shared by all blocks -> hits).
__global__ __launch_bounds__(256) void k_gemm128(const float* __restrict__ X,
                                                 const float* __restrict__ W,
                                                 float* __restrict__ C, int n) {
    __shared__ float xs[64 * FEAT];
    int t = threadIdx.x;
    int row0 = blockIdx.x * 64;

    for (int i = t; i < 64 * 32; i += 256) {
        int r  = i >> 5;
        int c4 = (i & 31) * 4;
        float4 v = make_float4(0.f, 0.f, 0.f, 0.f);
        if (row0 + r < n) v = *(const float4*)(X + (size_t)(row0 + r) * FEAT + c4);
        *(float4*)(xs + r * FEAT + c4) = v;
    }
    __syncthreads();

    int c4 = (t & 31) * 4;
    int rg = t >> 5;  // 0..7 (constant within warp -> smem broadcast)
    float4 acc[8];
#pragma unroll
    for (int j = 0; j < 8; j++) acc[j] = make_float4(0.f, 0.f, 0.f, 0.f);

    const float* xb = xs + (rg * 8) * FEAT;
    for (int k = 0; k < FEAT; k++) {
        float4 wv = __ldg((const float4*)(W + k * FEAT + c4));
#pragma unroll
        for (int j = 0; j < 8; j++) {
            float xv = xb[j * FEAT + k];
            acc[j].x = fmaf(xv, wv.x, acc[j].x);
            acc[j].y = fmaf(xv, wv.y, acc[j].y);
            acc[j].z = fmaf(xv, wv.z, acc[j].z);
            acc[j].w = fmaf(xv, wv.w, acc[j].w);
        }
    }
#pragma unroll
    for (int j = 0; j < 8; j++) {
        int row = row0 + rg * 8 + j;
        if (row < n) *(float4*)(C + (size_t)row * FEAT + c4) = acc[j];
    }
}

// ---------------- pull aggregation, 128 wide, fused bias+BN+ReLU ----------------
// One warp per node; lane handles 4 contiguous channels.
__global__ __launch_bounds__(256) void k_agg128(const float* __restrict__ h,
                                                float* __restrict__ out,
                                                int soff, int n) {
    int gw   = (blockIdx.x * blockDim.x + threadIdx.x) >> 5;
    int lane = threadIdx.x & 31;
    if (gw >= n) return;
    int node = gw;
    int beg = g_rowptr[node];
    int end = g_rowptr[node + 1];
    float dn = g_dinv[node];
    int c4 = lane * 4;

    float4 acc = *(const float4*)(h + (size_t)node * FEAT + c4);
    float w0 = dn * dn;  // self-loop norm
    acc.x *= w0; acc.y *= w0; acc.z *= w0; acc.w *= w0;

#pragma unroll 4
    for (int e = beg; e < end; e++) {
        int s   = g_csr_src[e];
        float w = g_csr_norm[e];
        float4 hv = __ldg((const float4*)(h + (size_t)s * FEAT + c4));
        acc.x = fmaf(w, hv.x, acc.x);
        acc.y = fmaf(w, hv.y, acc.y);
        acc.z = fmaf(w, hv.z, acc.z);
        acc.w = fmaf(w, hv.w, acc.w);
    }

    float4 sv = *(const float4*)(g_S + soff + c4);
    float4 tv = *(const float4*)(g_T + soff + c4);
    float4 o;
    o.x = fmaxf(fmaf(acc.x, sv.x, tv.x), 0.f);
    o.y = fmaxf(fmaf(acc.y, sv.y, tv.y), 0.f);
    o.z = fmaxf(fmaf(acc.z, sv.z, tv.z), 0.f);
    o.w = fmaxf(fmaf(acc.w, sv.w, tv.w), 0.f);
    *(float4*)(out + (size_t)node * FEAT + c4) = o;
}

// ---------------- GEMM: C[n,16] = X[n,128] @ W3[128,16] ----------------
__global__ __launch_bounds__(256) void k_gemm16(const float* __restrict__ X,
                                                const float* __restrict__ W,
                                                float* __restrict__ C, int n) {
    __shared__ float xs[64 * 132];  // pad stride 132 to avoid bank conflicts
    int t = threadIdx.x;
    int row0 = blockIdx.x * 64;

    for (int i = t; i < 64 * 32; i += 256) {
        int r  = i >> 5;
        int c4 = (i & 31) * 4;
        float4 v = make_float4(0.f, 0.f, 0.f, 0.f);
        if (row0 + r < n) v = *(const float4*)(X + (size_t)(row0 + r) * FEAT + c4);
        *(float4*)(xs + r * 132 + c4) = v;
    }
    __syncthreads();

    int c4  = (t & 3) * 4;   // 16 cols
    int row = t >> 2;        // 0..63
    float4 acc = make_float4(0.f, 0.f, 0.f, 0.f);
    const float* xr = xs + row * 132;
    for (int k = 0; k < FEAT; k++) {
        float4 wv = __ldg((const float4*)(W + k * OUTF + c4));
        float xv  = xr[k];
        acc.x = fmaf(xv, wv.x, acc.x);
        acc.y = fmaf(xv, wv.y, acc.y);
        acc.z = fmaf(xv, wv.z, acc.z);
        acc.w = fmaf(xv, wv.w, acc.w);
    }
    int r = row0 + row;
    if (r < n) *(float4*)(C + (size_t)r * OUTF + c4) = acc;
}

// ---------------- aggregation 16 wide + bias + log_softmax ----------------
// 4 lanes per node (quad); quad shuffle reduce for max / sumexp.
__global__ __launch_bounds__(256) void k_agg16(const float* __restrict__ h,
                                               const float* __restrict__ b3,
                                               float* __restrict__ out, int n) {
    int gi   = blockIdx.x * blockDim.x + threadIdx.x;
    int node = gi >> 2;
    int q    = gi & 3;
    if (node >= n) return;  // n*4 % 32 == 0 -> whole-warp exits, shfl below safe
    int beg = g_rowptr[node];
    int end = g_rowptr[node + 1];
    float dn = g_dinv[node];
    int c4 = q * 4;

    float4 acc = *(const float4*)(h + (size_t)node * OUTF + c4);
    float w0 = dn * dn;
    acc.x *= w0; acc.y *= w0; acc.z *= w0; acc.w *= w0;

#pragma unroll 4
    for (int e = beg; e < end; e++) {
        int s   = g_csr_src[e];
        float w = g_csr_norm[e];
        float4 hv = __ldg((const float4*)(h + (size_t)s * OUTF + c4));
        acc.x = fmaf(w, hv.x, acc.x);
        acc.y = fmaf(w, hv.y, acc.y);
        acc.z = fmaf(w, hv.z, acc.z);
        acc.w = fmaf(w, hv.w, acc.w);
    }

    float4 bv = *(const float4*)(b3 + c4);
    float z0 = acc.x + bv.x, z1 = acc.y + bv.y, z2 = acc.z + bv.z, z3 = acc.w + bv.w;

    float mx = fmaxf(fmaxf(z0, z1), fmaxf(z2, z3));
    mx = fmaxf(mx, __shfl_xor_sync(0xffffffffu, mx, 1));
    mx = fmaxf(mx, __shfl_xor_sync(0xffffffffu, mx, 2));

    float se = expf(z0 - mx) + expf(z1 - mx) + expf(z2 - mx) + expf(z3 - mx);
    se += __shfl_xor_sync(0xffffffffu, se, 1);
    se += __shfl_xor_sync(0xffffffffu, se, 2);
    float l = logf(se);

    float4 o;
    o.x = z0 - mx - l; o.y = z1 - mx - l; o.z = z2 - mx - l; o.w = z3 - mx - l;
    *(float4*)(out + (size_t)node * OUTF + c4) = o;
}

// ---------------- launch ----------------
extern "C" void kernel_launch(void* const* d_in, const int* in_sizes, int n_in,
                              void* d_out, int out_size) {
    const float* x   = (const float*)d_in[0];
    const int*   ei  = (const int*)d_in[1];   // int32: JAX demotes int64 w/o x64
    const float* W1  = (const float*)d_in[2];
    const float* b1  = (const float*)d_in[3];
    const float* g1  = (const float*)d_in[4];
    const float* be1 = (const float*)d_in[5];
    const float* m1  = (const float*)d_in[6];
    const float* v1  = (const float*)d_in[7];
    const float* W2  = (const float*)d_in[8];
    const float* b2  = (const float*)d_in[9];
    const float* g2  = (const float*)d_in[10];
    const float* be2 = (const float*)d_in[11];
    const float* m2  = (const float*)d_in[12];
    const float* v2  = (const float*)d_in[13];
    const float* W3  = (const float*)d_in[14];
    const float* b3  = (const float*)d_in[15];
    float*       out = (float*)d_out;

    // Resolve device-global scratch addresses (host code cannot reference
    // __device__ symbols directly as kernel args).
    void *ph = nullptr, *px2 = nullptr;
    cudaGetSymbolAddress(&ph,  g_h);
    cudaGetSymbolAddress(&px2, g_x2);
    float* h_buf  = (float*)ph;
    float* x2_buf = (float*)px2;

    int n = in_sizes[0] / FEAT;
    int e = in_sizes[1] / 2;

    int nb     = (n + 1023) / 1024;
    int nthr   = (n + 255) / 256;
    int ethr   = (e + 255) / 256;
    int gblk   = (n + 63) / 64;
    int ablk   = ((n * 32) + 255) / 256;   // warp per node
    int a16blk = ((n * 4) + 255) / 256;    // quad per node

    // graph prep
    k_zero_deg<<<nthr, 256>>>(n);
    k_count<<<ethr, 256>>>(ei, e, n);
    k_dinv<<<nthr, 256>>>(n);
    k_scan1<<<nb, 1024>>>(n);
    k_scan2<<<1, 1>>>(nb, n);
    k_scan3<<<nb, 1024>>>(n);
    k_fill<<<ethr, 256>>>(ei, e, n);
    k_prep<<<1, 256>>>(b1, g1, be1, m1, v1, b2, g2, be2, m2, v2);

    // layer 1
    k_gemm128<<<gblk, 256>>>(x, W1, h_buf, n);
    k_agg128<<<ablk, 256>>>(h_buf, x2_buf, 0, n);
    // layer 2
    k_gemm128<<<gblk, 256>>>(x2_buf, W2, h_buf, n);
    k_agg128<<<ablk, 256>>>(h_buf, x2_buf, FEAT, n);
    // layer 3
    k_gemm16<<<gblk, 256>>>(x2_buf, W3, h_buf, n);
    k_agg16<<<a16blk, 256>>>(h_buf, b3, out, n);
}

// round 4
// speedup vs baseline: 1.1509x; 1.1509x over previous
#include <cuda_runtime.h>
#include <math.h>
#include <stdint.h>

#define FEAT 128
#define OUTF 16
#define NMAX 50000
#define EMAX 800000
#define BN_EPS 1e-5f

typedef unsigned long long u64;

// ---------------- scratch (no allocations allowed) ----------------
__device__ float g_h[(size_t)NMAX * FEAT];     // GEMM output (layer3 reuses as [n,16])
__device__ float g_x2[(size_t)NMAX * FEAT];    // post-aggregation activation
__device__ int   g_deg[NMAX];                  // zero at module load; re-zeroed at tail
__device__ int   g_rowptr[NMAX + 1];
__device__ int   g_cursor[NMAX];
__device__ float g_dinv[NMAX];
__device__ int2  g_csr_sn[EMAX];               // packed (src, bitcast norm)
__device__ float g_S[2 * FEAT];
__device__ float g_T[2 * FEAT];
__device__ int   g_blksum[1024];

// ---------------- f32x2 packed-FMA helpers ----------------
__device__ __forceinline__ void ffma2(u64& d, u64 a, u64 b) {
    asm("fma.rn.f32x2 %0, %1, %2, %0;" : "+l"(d) : "l"(a), "l"(b));
}
__device__ __forceinline__ u64 pack2(float lo, float hi) {
    u64 r; asm("mov.b64 %0, {%1, %2};" : "=l"(r) : "f"(lo), "f"(hi)); return r;
}
__device__ __forceinline__ void unpack2(u64 v, float& lo, float& hi) {
    asm("mov.b64 {%0, %1}, %2;" : "=f"(lo), "=f"(hi) : "l"(v));
}

// ---------------- count degrees + (block 0) BN prep ----------------
__global__ void k_count_prep(const int* __restrict__ ei, int e, int n,
                             const float* __restrict__ b1, const float* __restrict__ g1,
                             const float* __restrict__ be1, const float* __restrict__ m1,
                             const float* __restrict__ v1,
                             const float* __restrict__ b2, const float* __restrict__ g2,
                             const float* __restrict__ be2, const float* __restrict__ m2,
                             const float* __restrict__ v2) {
    int i = blockIdx.x * blockDim.x + threadIdx.x;
    if (i < e) {
        int d = ei[e + i];
        d = min(max(d, 0), n - 1);
        atomicAdd(&g_deg[d], 1);
    }
    if (blockIdx.x == 0) {
        int t = threadIdx.x;
        if (t < FEAT) {
            float s = rsqrtf(v1[t] + BN_EPS) * g1[t];
            g_S[t] = s;
            g_T[t] = (b1[t] - m1[t]) * s + be1[t];
        } else if (t < 2 * FEAT) {
            int c = t - FEAT;
            float s = rsqrtf(v2[c] + BN_EPS) * g2[c];
            g_S[FEAT + c] = s;
            g_T[FEAT + c] = (b2[c] - m2[c]) * s + be2[c];
        }
    }
}

// ---------------- scan stage 1 (+ dinv fused) ----------------
__global__ void k_scan1(int n) {
    __shared__ int sm[1024];
    int t = threadIdx.x;
    int i = blockIdx.x * 1024 + t;
    int v = (i < n) ? g_deg[i] : 0;
    if (i < n) g_dinv[i] = rsqrtf((float)(v + 1));  // +1 self loop
    sm[t] = v;
    __syncthreads();
    for (int off = 512; off > 0; off >>= 1) {
        if (t < off) sm[t] += sm[t + off];
        __syncthreads();
    }
    if (t == 0) g_blksum[blockIdx.x] = sm[0];
}

__global__ void k_scan2(int nb, int n) {  // <<<1,1>>>
    int running = 0;
    for (int b = 0; b < nb; b++) {
        int v = g_blksum[b];
        g_blksum[b] = running;
        running += v;
    }
    g_rowptr[n] = running;
}

__global__ void k_scan3(int n) {
    __shared__ int sm[1024];
    int t = threadIdx.x;
    int i = blockIdx.x * 1024 + t;
    int v = (i < n) ? g_deg[i] : 0;
    sm[t] = v;
    __syncthreads();
    for (int off = 1; off < 1024; off <<= 1) {
        int u = 0;
        if (t >= off) u = sm[t - off];
        __syncthreads();
        sm[t] += u;
        __syncthreads();
    }
    if (i < n) {
        int excl = g_blksum[blockIdx.x] + sm[t] - v;
        g_rowptr[i] = excl;
        g_cursor[i] = excl;
    }
}

__global__ void k_fill(const int* __restrict__ ei, int e, int n) {
    int i = blockIdx.x * blockDim.x + threadIdx.x;
    if (i < e) {
        int s = ei[i];
        int d = ei[e + i];
        s = min(max(s, 0), n - 1);
        d = min(max(d, 0), n - 1);
        int p = atomicAdd(&g_cursor[d], 1);
        float w = g_dinv[s] * g_dinv[d];
        g_csr_sn[p] = make_int2(s, __float_as_int(w));
    }
}

__global__ void k_zero_deg(int n) {  // tail: restore invariant for next call
    int i = blockIdx.x * blockDim.x + threadIdx.x;
    if (i < n) g_deg[i] = 0;
}

// ---------------- GEMM: C[n,128] = X[n,128] @ W[128,128], fp32 via f32x2 ----------------
// 256 threads, 64 rows x 128 cols per block. X tile stored TRANSPOSED in smem
// (xs_t[k][r]) so row-pairs load as one broadcast ld.shared.b64. Inner loop:
// 16 FFMA2 + 4 LDS.64 + 4 dups per k (vs 32 FFMA + 8 LDS scalar).
__global__ __launch_bounds__(256, 2) void k_gemm128(const float* __restrict__ X,
                                                    const float* __restrict__ W,
                                                    float* __restrict__ C, int n) {
    __shared__ __align__(16) float xs_t[FEAT * 64];  // [k][r] = k*64 + r
    int t = threadIdx.x;
    int row0 = blockIdx.x * 64;

    // Loader: thread = (row r, 128B col chunk cg). Transposed stores are
    // conflict-free (bank = r % 32, distinct across warp lanes).
    {
        int r  = t & 63;
        int cg = t >> 6;  // 0..3
        int grow = row0 + r;
        const float4* src = (const float4*)(X + (size_t)grow * FEAT + cg * 32);
        bool ok = grow < n;
#pragma unroll
        for (int u = 0; u < 8; u++) {
            float4 v = ok ? __ldg(src + u) : make_float4(0.f, 0.f, 0.f, 0.f);
            int k0 = cg * 32 + u * 4;
            xs_t[(k0 + 0) * 64 + r] = v.x;
            xs_t[(k0 + 1) * 64 + r] = v.y;
            xs_t[(k0 + 2) * 64 + r] = v.z;
            xs_t[(k0 + 3) * 64 + r] = v.w;
        }
    }
    __syncthreads();

    int c4 = (t & 31) * 4;
    int rg = t >> 5;  // 0..7 -> rows rg*8 .. rg*8+7 as 4 packed pairs

    u64 acc[4][4];
#pragma unroll
    for (int j = 0; j < 4; j++)
#pragma unroll
        for (int c = 0; c < 4; c++) acc[j][c] = 0ull;

    const float* xbase = xs_t + rg * 8;
#pragma unroll 4
    for (int k = 0; k < FEAT; k++) {
        float4 wv = __ldg((const float4*)(W + k * FEAT + c4));
        u64 wd0 = pack2(wv.x, wv.x);
        u64 wd1 = pack2(wv.y, wv.y);
        u64 wd2 = pack2(wv.z, wv.z);
        u64 wd3 = pack2(wv.w, wv.w);
        const float* xc = xbase + k * 64;
        u64 xp0 = *(const u64*)(xc + 0);
        u64 xp1 = *(const u64*)(xc + 2);
        u64 xp2 = *(const u64*)(xc + 4);
        u64 xp3 = *(const u64*)(xc + 6);
        ffma2(acc[0][0], xp0, wd0); ffma2(acc[0][1], xp0, wd1);
        ffma2(acc[0][2], xp0, wd2); ffma2(acc[0][3], xp0, wd3);
        ffma2(acc[1][0], xp1, wd0); ffma2(acc[1][1], xp1, wd1);
        ffma2(acc[1][2], xp1, wd2); ffma2(acc[1][3], xp1, wd3);
        ffma2(acc[2][0], xp2, wd0); ffma2(acc[2][1], xp2, wd1);
        ffma2(acc[2][2], xp2, wd2); ffma2(acc[2][3], xp2, wd3);
        ffma2(acc[3][0], xp3, wd0); ffma2(acc[3][1], xp3, wd1);
        ffma2(acc[3][2], xp3, wd2); ffma2(acc[3][3], xp3, wd3);
    }

#pragma unroll
    for (int j = 0; j < 4; j++) {
        float l0, h0, l1, h1, l2, h2, l3, h3;
        unpack2(acc[j][0], l0, h0);
        unpack2(acc[j][1], l1, h1);
        unpack2(acc[j][2], l2, h2);
        unpack2(acc[j][3], l3, h3);
        int r0 = row0 + rg * 8 + 2 * j;
        if (r0 < n)
            *(float4*)(C + (size_t)r0 * FEAT + c4) = make_float4(l0, l1, l2, l3);
        if (r0 + 1 < n)
            *(float4*)(C + (size_t)(r0 + 1) * FEAT + c4) = make_float4(h0, h1, h2, h3);
    }
}

// ---------------- pull aggregation, 128 wide, fused bias+BN+ReLU ----------------
__global__ __launch_bounds__(256) void k_agg128(const float* __restrict__ h,
                                                float* __restrict__ out,
                                                int soff, int n) {
    int gw   = (blockIdx.x * blockDim.x + threadIdx.x) >> 5;
    int lane = threadIdx.x & 31;
    if (gw >= n) return;
    int node = gw;
    int beg = g_rowptr[node];
    int end = g_rowptr[node + 1];
    float dn = g_dinv[node];
    int c4 = lane * 4;

    float4 acc = *(const float4*)(h + (size_t)node * FEAT + c4);
    float w0 = dn * dn;  // self-loop norm
    acc.x *= w0; acc.y *= w0; acc.z *= w0; acc.w *= w0;

#pragma unroll 4
    for (int e = beg; e < end; e++) {
        int2 p  = __ldg(&g_csr_sn[e]);
        int   s = p.x;
        float w = __int_as_float(p.y);
        float4 hv = __ldg((const float4*)(h + (size_t)s * FEAT + c4));
        acc.x = fmaf(w, hv.x, acc.x);
        acc.y = fmaf(w, hv.y, acc.y);
        acc.z = fmaf(w, hv.z, acc.z);
        acc.w = fmaf(w, hv.w, acc.w);
    }

    float4 sv = *(const float4*)(g_S + soff + c4);
    float4 tv = *(const float4*)(g_T + soff + c4);
    float4 o;
    o.x = fmaxf(fmaf(acc.x, sv.x, tv.x), 0.f);
    o.y = fmaxf(fmaf(acc.y, sv.y, tv.y), 0.f);
    o.z = fmaxf(fmaf(acc.z, sv.z, tv.z), 0.f);
    o.w = fmaxf(fmaf(acc.w, sv.w, tv.w), 0.f);
    *(float4*)(out + (size_t)node * FEAT + c4) = o;
}

// ---------------- GEMM: C[n,16] = X[n,128] @ W3[128,16] ----------------
__global__ __launch_bounds__(256) void k_gemm16(const float* __restrict__ X,
                                                const float* __restrict__ W,
                                                float* __restrict__ C, int n) {
    __shared__ float xs[64 * 132];
    int t = threadIdx.x;
    int row0 = blockIdx.x * 64;

    for (int i = t; i < 64 * 32; i += 256) {
        int r  = i >> 5;
        int c4 = (i & 31) * 4;
        float4 v = make_float4(0.f, 0.f, 0.f, 0.f);
        if (row0 + r < n) v = *(const float4*)(X + (size_t)(row0 + r) * FEAT + c4);
        *(float4*)(xs + r * 132 + c4) = v;
    }
    __syncthreads();

    int c4  = (t & 3) * 4;
    int row = t >> 2;
    float4 acc = make_float4(0.f, 0.f, 0.f, 0.f);
    const float* xr = xs + row * 132;
#pragma unroll 4
    for (int k = 0; k < FEAT; k++) {
        float4 wv = __ldg((const float4*)(W + k * OUTF + c4));
        float xv  = xr[k];
        acc.x = fmaf(xv, wv.x, acc.x);
        acc.y = fmaf(xv, wv.y, acc.y);
        acc.z = fmaf(xv, wv.z, acc.z);
        acc.w = fmaf(xv, wv.w, acc.w);
    }
    int r = row0 + row;
    if (r < n) *(float4*)(C + (size_t)r * OUTF + c4) = acc;
}

// ---------------- aggregation 16 wide + bias + log_softmax ----------------
__global__ __launch_bounds__(256) void k_agg16(const float* __restrict__ h,
                                               const float* __restrict__ b3,
                                               float* __restrict__ out, int n) {
    int gi   = blockIdx.x * blockDim.x + threadIdx.x;
    int node = gi >> 2;
    int q    = gi & 3;
    if (node >= n) return;
    int beg = g_rowptr[node];
    int end = g_rowptr[node + 1];
    float dn = g_dinv[node];
    int c4 = q * 4;

    float4 acc = *(const float4*)(h + (size_t)node * OUTF + c4);
    float w0 = dn * dn;
    acc.x *= w0; acc.y *= w0; acc.z *= w0; acc.w *= w0;

#pragma unroll 4
    for (int e = beg; e < end; e++) {
        int2 p  = __ldg(&g_csr_sn[e]);
        int   s = p.x;
        float w = __int_as_float(p.y);
        float4 hv = __ldg((const float4*)(h + (size_t)s * OUTF + c4));
        acc.x = fmaf(w, hv.x, acc.x);
        acc.y = fmaf(w, hv.y, acc.y);
        acc.z = fmaf(w, hv.z, acc.z);
        acc.w = fmaf(w, hv.w, acc.w);
    }

    float4 bv = *(const float4*)(b3 + c4);
    float z0 = acc.x + bv.x, z1 = acc.y + bv.y, z2 = acc.z + bv.z, z3 = acc.w + bv.w;

    float mx = fmaxf(fmaxf(z0, z1), fmaxf(z2, z3));
    mx = fmaxf(mx, __shfl_xor_sync(0xffffffffu, mx, 1));
    mx = fmaxf(mx, __shfl_xor_sync(0xffffffffu, mx, 2));

    float se = expf(z0 - mx) + expf(z1 - mx) + expf(z2 - mx) + expf(z3 - mx);
    se += __shfl_xor_sync(0xffffffffu, se, 1);
    se += __shfl_xor_sync(0xffffffffu, se, 2);
    float l = logf(se);

    float4 o;
    o.x = z0 - mx - l; o.y = z1 - mx - l; o.z = z2 - mx - l; o.w = z3 - mx - l;
    *(float4*)(out + (size_t)node * OUTF + c4) = o;
}

// ---------------- launch ----------------
extern "C" void kernel_launch(void* const* d_in, const int* in_sizes, int n_in,
                              void* d_out, int out_size) {
    const float* x   = (const float*)d_in[0];
    const int*   ei  = (const int*)d_in[1];   // int32 (JAX x64-disabled)
    const float* W1  = (const float*)d_in[2];
    const float* b1  = (const float*)d_in[3];
    const float* g1  = (const float*)d_in[4];
    const float* be1 = (const float*)d_in[5];
    const float* m1  = (const float*)d_in[6];
    const float* v1  = (const float*)d_in[7];
    const float* W2  = (const float*)d_in[8];
    const float* b2  = (const float*)d_in[9];
    const float* g2  = (const float*)d_in[10];
    const float* be2 = (const float*)d_in[11];
    const float* m2  = (const float*)d_in[12];
    const float* v2  = (const float*)d_in[13];
    const float* W3  = (const float*)d_in[14];
    const float* b3  = (const float*)d_in[15];
    float*       out = (float*)d_out;

    void *ph = nullptr, *px2 = nullptr;
    cudaGetSymbolAddress(&ph,  g_h);
    cudaGetSymbolAddress(&px2, g_x2);
    float* h_buf  = (float*)ph;
    float* x2_buf = (float*)px2;

    int n = in_sizes[0] / FEAT;
    int e = in_sizes[1] / 2;

    int nb     = (n + 1023) / 1024;
    int nthr   = (n + 255) / 256;
    int ethr   = (e + 255) / 256;
    int gblk   = (n + 63) / 64;
    int ablk   = ((n * 32) + 255) / 256;
    int a16blk = ((n * 4) + 255) / 256;

    // CSR build (g_deg is zero: module-load init on call 1, tail-zero after).
    k_count_prep<<<ethr, 256>>>(ei, e, n, b1, g1, be1, m1, v1, b2, g2, be2, m2, v2);
    k_scan1<<<nb, 1024>>>(n);
    k_scan2<<<1, 1>>>(nb, n);
    k_scan3<<<nb, 1024>>>(n);
    k_fill<<<ethr, 256>>>(ei, e, n);

    // layers (launch idx 5 = gemm128 L1 -> ncu -s 5 profiles it)
    k_gemm128<<<gblk, 256>>>(x, W1, h_buf, n);
    k_agg128<<<ablk, 256>>>(h_buf, x2_buf, 0, n);
    k_gemm128<<<gblk, 256>>>(x2_buf, W2, h_buf, n);
    k_agg128<<<ablk, 256>>>(h_buf, x2_buf, FEAT, n);
    k_gemm16<<<gblk, 256>>>(x2_buf, W3, h_buf, n);
    k_agg16<<<a16blk, 256>>>(h_buf, b3, out, n);

    // restore degree invariant for next call
    k_zero_deg<<<nthr, 256>>>(n);
}

// round 5
// speedup vs baseline: 1.1757x; 1.0216x over previous
#include <cuda_runtime.h>
#include <math.h>
#include <stdint.h>

#define FEAT 128
#define OUTF 16
#define NMAX 50000
#define EMAX 800000
#define BN_EPS 1e-5f

typedef unsigned long long u64;

// ---------------- scratch (no allocations allowed) ----------------
__device__ float g_h[(size_t)NMAX * FEAT];     // GEMM output (layer3 reuses as [n,16])
__device__ float g_x2[(size_t)NMAX * FEAT];    // post-aggregation activation
__device__ int   g_deg[NMAX];                  // zero at module load; re-zeroed by agg16
__device__ int   g_rowptr[NMAX + 1];
__device__ int   g_cursor[NMAX];
__device__ float g_dinv[NMAX];
__device__ int2  g_csr_sn[EMAX];               // packed (src, bitcast norm)
__device__ float g_S[2 * FEAT];
__device__ float g_T[2 * FEAT];
__device__ int   g_blksum[64];

// ---------------- f32x2 packed-FMA helpers ----------------
__device__ __forceinline__ void ffma2(u64& d, u64 a, u64 b) {
    asm("fma.rn.f32x2 %0, %1, %2, %0;" : "+l"(d) : "l"(a), "l"(b));
}
__device__ __forceinline__ u64 pack2(float lo, float hi) {
    u64 r; asm("mov.b64 %0, {%1, %2};" : "=l"(r) : "f"(lo), "f"(hi)); return r;
}
__device__ __forceinline__ void unpack2(u64 v, float& lo, float& hi) {
    asm("mov.b64 {%0, %1}, %2;" : "=f"(lo), "=f"(hi) : "l"(v));
}

// ---------------- shared GEMM-128 block body (fp32 via f32x2) ----------------
// 256 threads, 64 rows x 128 cols. X tile stored TRANSPOSED in smem so
// row-pairs load as one broadcast ld.shared.b64.
__device__ __forceinline__ void gemm128_block(const float* __restrict__ X,
                                              const float* __restrict__ W,
                                              float* __restrict__ C,
                                              int n, int row0) {
    __shared__ __align__(16) float xs_t[FEAT * 64];  // [k][r]
    int t = threadIdx.x;
    {
        int r  = t & 63;
        int cg = t >> 6;  // 0..3
        int grow = row0 + r;
        const float4* src = (const float4*)(X + (size_t)grow * FEAT + cg * 32);
        bool ok = grow < n;
#pragma unroll
        for (int u = 0; u < 8; u++) {
            float4 v = ok ? __ldg(src + u) : make_float4(0.f, 0.f, 0.f, 0.f);
            int k0 = cg * 32 + u * 4;
            xs_t[(k0 + 0) * 64 + r] = v.x;
            xs_t[(k0 + 1) * 64 + r] = v.y;
            xs_t[(k0 + 2) * 64 + r] = v.z;
            xs_t[(k0 + 3) * 64 + r] = v.w;
        }
    }
    __syncthreads();

    int c4 = (t & 31) * 4;
    int rg = t >> 5;  // 0..7

    u64 acc[4][4];
#pragma unroll
    for (int j = 0; j < 4; j++)
#pragma unroll
        for (int c = 0; c < 4; c++) acc[j][c] = 0ull;

    const float* xbase = xs_t + rg * 8;
#pragma unroll 4
    for (int k = 0; k < FEAT; k++) {
        float4 wv = __ldg((const float4*)(W + k * FEAT + c4));
        u64 wd0 = pack2(wv.x, wv.x);
        u64 wd1 = pack2(wv.y, wv.y);
        u64 wd2 = pack2(wv.z, wv.z);
        u64 wd3 = pack2(wv.w, wv.w);
        const float* xc = xbase + k * 64;
        u64 xp0 = *(const u64*)(xc + 0);
        u64 xp1 = *(const u64*)(xc + 2);
        u64 xp2 = *(const u64*)(xc + 4);
        u64 xp3 = *(const u64*)(xc + 6);
        ffma2(acc[0][0], xp0, wd0); ffma2(acc[0][1], xp0, wd1);
        ffma2(acc[0][2], xp0, wd2); ffma2(acc[0][3], xp0, wd3);
        ffma2(acc[1][0], xp1, wd0); ffma2(acc[1][1], xp1, wd1);
        ffma2(acc[1][2], xp1, wd2); ffma2(acc[1][3], xp1, wd3);
        ffma2(acc[2][0], xp2, wd0); ffma2(acc[2][1], xp2, wd1);
        ffma2(acc[2][2], xp2, wd2); ffma2(acc[2][3], xp2, wd3);
        ffma2(acc[3][0], xp3, wd0); ffma2(acc[3][1], xp3, wd1);
        ffma2(acc[3][2], xp3, wd2); ffma2(acc[3][3], xp3, wd3);
    }

#pragma unroll
    for (int j = 0; j < 4; j++) {
        float l0, h0, l1, h1, l2, h2, l3, h3;
        unpack2(acc[j][0], l0, h0);
        unpack2(acc[j][1], l1, h1);
        unpack2(acc[j][2], l2, h2);
        unpack2(acc[j][3], l3, h3);
        int r0 = row0 + rg * 8 + 2 * j;
        if (r0 < n)
            *(float4*)(C + (size_t)r0 * FEAT + c4) = make_float4(l0, l1, l2, l3);
        if (r0 + 1 < n)
            *(float4*)(C + (size_t)(r0 + 1) * FEAT + c4) = make_float4(h0, h1, h2, h3);
    }
}

// ---------------- K1: GEMM L1 rows [0, gA*64) || degree count || BN prep ----------------
__global__ __launch_bounds__(256, 2)
void k_fused1(const float* __restrict__ X, const float* __restrict__ W,
              float* __restrict__ C, int n, int gA,
              const int* __restrict__ ei, int e,
              const float* __restrict__ b1, const float* __restrict__ g1,
              const float* __restrict__ be1, const float* __restrict__ m1,
              const float* __restrict__ v1,
              const float* __restrict__ b2, const float* __restrict__ g2,
              const float* __restrict__ be2, const float* __restrict__ m2,
              const float* __restrict__ v2) {
    if ((int)blockIdx.x < gA) {
        gemm128_block(X, W, C, n, blockIdx.x * 64);
        return;
    }
    int cb = blockIdx.x - gA;
    int i  = cb * 256 + threadIdx.x;
    if (i < e) {
        int d = ei[e + i];
        d = min(max(d, 0), n - 1);
        atomicAdd(&g_deg[d], 1);
    }
    if (cb == 0) {
        int t = threadIdx.x;
        if (t < FEAT) {
            float s = rsqrtf(v1[t] + BN_EPS) * g1[t];
            g_S[t] = s;
            g_T[t] = (b1[t] - m1[t]) * s + be1[t];
        } else if (t < 2 * FEAT) {
            int c = t - FEAT;
            float s = rsqrtf(v2[c] + BN_EPS) * g2[c];
            g_S[FEAT + c] = s;
            g_T[FEAT + c] = (b2[c] - m2[c]) * s + be2[c];
        }
    }
}

// ---------------- scan stage 1 (+ dinv fused) ----------------
__global__ void k_scan1(int n) {
    __shared__ int sm[1024];
    int t = threadIdx.x;
    int i = blockIdx.x * 1024 + t;
    int v = (i < n) ? g_deg[i] : 0;
    if (i < n) g_dinv[i] = rsqrtf((float)(v + 1));  // +1 self loop
    sm[t] = v;
    __syncthreads();
    for (int off = 512; off > 0; off >>= 1) {
        if (t < off) sm[t] += sm[t + off];
        __syncthreads();
    }
    if (t == 0) g_blksum[blockIdx.x] = sm[0];
}

// ---------------- scan stage 2+3 merged: rowptr/cursor ----------------
__global__ void k_scan3(int n, int nb) {
    __shared__ int sm[1024];
    __shared__ int bs[64];
    int t   = threadIdx.x;
    int bid = blockIdx.x;
    int i   = bid * 1024 + t;
    if (t < nb) bs[t] = g_blksum[t];
    int v = (i < n) ? g_deg[i] : 0;
    sm[t] = v;
    __syncthreads();

    // per-thread prefix over block sums (<=64 independent smem adds)
    int pref = 0;
    for (int b = 0; b < bid; b++) pref += bs[b];

    for (int off = 1; off < 1024; off <<= 1) {
        int u = 0;
        if (t >= off) u = sm[t - off];
        __syncthreads();
        sm[t] += u;
        __syncthreads();
    }
    if (i < n) {
        int excl = pref + sm[t] - v;
        g_rowptr[i] = excl;
        g_cursor[i] = excl;
    }
    if (bid == nb - 1 && t == 0) {
        int total = pref;
        for (int b = bid; b < nb; b++) total += bs[b];
        g_rowptr[n] = total;
    }
}

// ---------------- K2: GEMM L1 rows [gA*64, n) || CSR fill ----------------
__global__ __launch_bounds__(256, 2)
void k_fused2(const float* __restrict__ X, const float* __restrict__ W,
              float* __restrict__ C, int n, int gA, int gB,
              const int* __restrict__ ei, int e) {
    if ((int)blockIdx.x < gB) {
        gemm128_block(X, W, C, n, (gA + blockIdx.x) * 64);
        return;
    }
    int i = (blockIdx.x - gB) * 256 + threadIdx.x;
    if (i < e) {
        int s = ei[i];
        int d = ei[e + i];
        s = min(max(s, 0), n - 1);
        d = min(max(d, 0), n - 1);
        int p = atomicAdd(&g_cursor[d], 1);
        float w = g_dinv[s] * g_dinv[d];
        g_csr_sn[p] = make_int2(s, __float_as_int(w));
    }
}

// ---------------- pull aggregation, 128 wide, fused bias+BN+ReLU ----------------
__global__ __launch_bounds__(256) void k_agg128(const float* __restrict__ h,
                                                float* __restrict__ out,
                                                int soff, int n) {
    int gw   = (blockIdx.x * blockDim.x + threadIdx.x) >> 5;
    int lane = threadIdx.x & 31;
    if (gw >= n) return;
    int node = gw;
    int beg = g_rowptr[node];
    int end = g_rowptr[node + 1];
    float dn = g_dinv[node];
    int c4 = lane * 4;

    float4 acc = *(const float4*)(h + (size_t)node * FEAT + c4);
    float w0 = dn * dn;  // self-loop norm
    acc.x *= w0; acc.y *= w0; acc.z *= w0; acc.w *= w0;

#pragma unroll 4
    for (int e = beg; e < end; e++) {
        int2 p  = __ldg(&g_csr_sn[e]);
        int   s = p.x;
        float w = __int_as_float(p.y);
        float4 hv = __ldg((const float4*)(h + (size_t)s * FEAT + c4));
        acc.x = fmaf(w, hv.x, acc.x);
        acc.y = fmaf(w, hv.y, acc.y);
        acc.z = fmaf(w, hv.z, acc.z);
        acc.w = fmaf(w, hv.w, acc.w);
    }

    float4 sv = *(const float4*)(g_S + soff + c4);
    float4 tv = *(const float4*)(g_T + soff + c4);
    float4 o;
    o.x = fmaxf(fmaf(acc.x, sv.x, tv.x), 0.f);
    o.y = fmaxf(fmaf(acc.y, sv.y, tv.y), 0.f);
    o.z = fmaxf(fmaf(acc.z, sv.z, tv.z), 0.f);
    o.w = fmaxf(fmaf(acc.w, sv.w, tv.w), 0.f);
    *(float4*)(out + (size_t)node * FEAT + c4) = o;
}

// ---------------- GEMM: C[n,16] = X[n,128] @ W3[128,16] ----------------
__global__ __launch_bounds__(256) void k_gemm16(const float* __restrict__ X,
                                                const float* __restrict__ W,
                                                float* __restrict__ C, int n) {
    __shared__ float xs[64 * 132];
    int t = threadIdx.x;
    int row0 = blockIdx.x * 64;

    for (int i = t; i < 64 * 32; i += 256) {
        int r  = i >> 5;
        int c4 = (i & 31) * 4;
        float4 v = make_float4(0.f, 0.f, 0.f, 0.f);
        if (row0 + r < n) v = *(const float4*)(X + (size_t)(row0 + r) * FEAT + c4);
        *(float4*)(xs + r * 132 + c4) = v;
    }
    __syncthreads();

    int c4  = (t & 3) * 4;
    int row = t >> 2;
    float4 acc = make_float4(0.f, 0.f, 0.f, 0.f);
    const float* xr = xs + row * 132;
#pragma unroll 4
    for (int k = 0; k < FEAT; k++) {
        float4 wv = __ldg((const float4*)(W + k * OUTF + c4));
        float xv  = xr[k];
        acc.x = fmaf(xv, wv.x, acc.x);
        acc.y = fmaf(xv, wv.y, acc.y);
        acc.z = fmaf(xv, wv.z, acc.z);
        acc.w = fmaf(xv, wv.w, acc.w);
    }
    int r = row0 + row;
    if (r < n) *(float4*)(C + (size_t)r * OUTF + c4) = acc;
}

// ---------------- aggregation 16 wide + bias + log_softmax (+ deg re-zero) ----------------
__global__ __launch_bounds__(256) void k_agg16(const float* __restrict__ h,
                                               const float* __restrict__ b3,
                                               float* __restrict__ out, int n) {
    int gi   = blockIdx.x * blockDim.x + threadIdx.x;
    int node = gi >> 2;
    int q    = gi & 3;
    if (node >= n) return;
    if (q == 0) g_deg[node] = 0;  // restore invariant for next call
    int beg = g_rowptr[node];
    int end = g_rowptr[node + 1];
    float dn = g_dinv[node];
    int c4 = q * 4;

    float4 acc = *(const float4*)(h + (size_t)node * OUTF + c4);
    float w0 = dn * dn;
    acc.x *= w0; acc.y *= w0; acc.z *= w0; acc.w *= w0;

#pragma unroll 4
    for (int e = beg; e < end; e++) {
        int2 p  = __ldg(&g_csr_sn[e]);
        int   s = p.x;
        float w = __int_as_float(p.y);
        float4 hv = __ldg((const float4*)(h + (size_t)s * OUTF + c4));
        acc.x = fmaf(w, hv.x, acc.x);
        acc.y = fmaf(w, hv.y, acc.y);
        acc.z = fmaf(w, hv.z, acc.z);
        acc.w = fmaf(w, hv.w, acc.w);
    }

    float4 bv = *(const float4*)(b3 + c4);
    float z0 = acc.x + bv.x, z1 = acc.y + bv.y, z2 = acc.z + bv.z, z3 = acc.w + bv.w;

    float mx = fmaxf(fmaxf(z0, z1), fmaxf(z2, z3));
    mx = fmaxf(mx, __shfl_xor_sync(0xffffffffu, mx, 1));
    mx = fmaxf(mx, __shfl_xor_sync(0xffffffffu, mx, 2));

    float se = expf(z0 - mx) + expf(z1 - mx) + expf(z2 - mx) + expf(z3 - mx);
    se += __shfl_xor_sync(0xffffffffu, se, 1);
    se += __shfl_xor_sync(0xffffffffu, se, 2);
    float l = logf(se);

    float4 o;
    o.x = z0 - mx - l; o.y = z1 - mx - l; o.z = z2 - mx - l; o.w = z3 - mx - l;
    *(float4*)(out + (size_t)node * OUTF + c4) = o;
}

// ---------------- launch ----------------
extern "C" void kernel_launch(void* const* d_in, const int* in_sizes, int n_in,
                              void* d_out, int out_size) {
    const float* x   = (const float*)d_in[0];
    const int*   ei  = (const int*)d_in[1];   // int32 (JAX x64-disabled)
    const float* W1  = (const float*)d_in[2];
    const float* b1  = (const float*)d_in[3];
    const float* g1  = (const float*)d_in[4];
    const float* be1 = (const float*)d_in[5];
    const float* m1  = (const float*)d_in[6];
    const float* v1  = (const float*)d_in[7];
    const float* W2  = (const float*)d_in[8];
    const float* b2  = (const float*)d_in[9];
    const float* g2  = (const float*)d_in[10];
    const float* be2 = (const float*)d_in[11];
    const float* m2  = (const float*)d_in[12];
    const float* v2  = (const float*)d_in[13];
    const float* W3  = (const float*)d_in[14];
    const float* b3  = (const float*)d_in[15];
    float*       out = (float*)d_out;

    void *ph = nullptr, *px2 = nullptr;
    cudaGetSymbolAddress(&ph,  g_h);
    cudaGetSymbolAddress(&px2, g_x2);
    float* h_buf  = (float*)ph;
    float* x2_buf = (float*)px2;

    int n = in_sizes[0] / FEAT;
    int e = in_sizes[1] / 2;

    int nb     = (n + 1023) / 1024;
    int ethr   = (e + 255) / 256;
    int gblk   = (n + 63) / 64;
    int gA     = gblk / 2;           // GEMM L1 first half
    int gB     = gblk - gA;          // GEMM L1 second half
    int ablk   = ((n * 32) + 255) / 256;
    int a16blk = ((n * 4) + 255) / 256;

    // K1: gemm L1 (A) + degree count + BN prep   (g_deg zero on entry)
    k_fused1<<<gA + ethr, 256>>>(x, W1, h_buf, n, gA, ei, e,
                                 b1, g1, be1, m1, v1, b2, g2, be2, m2, v2);
    k_scan1<<<nb, 1024>>>(n);
    k_scan3<<<nb, 1024>>>(n, nb);
    // K2: gemm L1 (B) + CSR fill
    k_fused2<<<gB + ethr, 256>>>(x, W1, h_buf, n, gA, gB, ei, e);

    k_agg128<<<ablk, 256>>>(h_buf, x2_buf, 0, n);
    gemm128_block_launch:
    { }
    // layer 2
    k_fused2<<<gblk, 256>>>(x2_buf, W2, h_buf, n, 0, gblk, ei, 0);  // pure gemm (no fill blocks)
    k_agg128<<<ablk, 256>>>(h_buf, x2_buf, FEAT, n);
    // layer 3
    k_gemm16<<<gblk, 256>>>(x2_buf, W3, h_buf, n);
    k_agg16<<<a16blk, 256>>>(h_buf, b3, out, n);
}